// round 17
// baseline (speedup 1.0000x reference)
#include <cuda_runtime.h>
#include <cstdint>

#define Vv 50000
#define Dd 300
#define Hh 512
#define Gg 2048
#define Bb 32
#define LCc 400
#define LQ1 29
#define NR 928
#define NRPAD 960
#define NEGLOGV -10.8197782844103f

// persistent-LSTM geometry: 4 independent groups x 32 blocks
#define GRP  4
#define GBLK 32
#define KPB  16     // k per block
#define BPG  8      // batches per group
#define WSTR 516    // smem row stride (floats): 16B-aligned, rows 16B apart in banks
#define WS_F2   (64*WSTR)
#define HS_OFF2 WS_F2
#define SACC_OFF2 (WS_F2 + BPG*WSTR)
#define SMEM_P2 ((WS_F2 + BPG*WSTR + 4*64*9)*4)

// ---------------- device scratch ----------------
__device__ __align__(16) float g_MT[2][150*4096];            // [which][d/2][g][d&1]
__device__ __align__(16) float g_xgE[(size_t)LCc*Gg*Bb];     // [t][g][b]
__device__ __align__(16) float g_xgD[(size_t)LQ1*Gg*Bb];     // [t][g][b]
__device__ __align__(16) float g_h[2][Bb*Hh];                // [b][k]
__device__ __align__(16) float g_c[Hh*Bb];                   // [k*32+b]
__device__ __align__(16) float g_dech[(size_t)NRPAD*Hh];     // [(b*29+t)][k]
__device__ int g_clen[Bb];
__device__ __align__(128) unsigned g_flags[GRP*GBLK];        // per-group flag line (128B each)

// ---------------- helpers ----------------
__device__ __forceinline__ void fma2(unsigned long long &a, unsigned long long x, unsigned long long y){
    asm("fma.rn.f32x2 %0, %1, %2, %0;" : "+l"(a) : "l"(x), "l"(y));
}
__device__ __forceinline__ float2 up2(unsigned long long v){
    float2 f; asm("mov.b64 {%0,%1}, %2;" : "=f"(f.x), "=f"(f.y) : "l"(v)); return f;
}
__device__ __forceinline__ unsigned long long pack2(float x){
    unsigned long long r; asm("mov.b64 %0, {%1, %1};" : "=l"(r) : "f"(x)); return r;
}
__device__ __forceinline__ ulonglong2 ldcg128(const ulonglong2* p){
    ulonglong2 r;
    asm volatile("ld.global.cg.v2.u64 {%0,%1},[%2];" : "=l"(r.x), "=l"(r.y) : "l"(p));
    return r;
}
__device__ __forceinline__ unsigned ldvol(const unsigned* p){
    unsigned v;
    asm volatile("ld.volatile.global.u32 %0,[%1];" : "=r"(v) : "l"(p));
    return v;
}

__global__ void k_clen(const int* __restrict__ cw){
    int tid = threadIdx.x, b = tid>>3, sub = tid&7, s = 0;
    for (int t = sub; t < LCc; t += 8) s += (cw[b*LCc+t] != 0);
    __shared__ int r[256];
    r[tid] = s; __syncthreads();
    if (sub == 0){ int tot = 0;
        #pragma unroll
        for (int u = 0; u < 8; u++) tot += r[tid+u];
        g_clen[b] = tot; }
}

__global__ void k_zero(){
    int i = blockIdx.x*256 + threadIdx.x;
    if (i < Bb*Hh){ g_h[0][i] = 0.f; g_h[1][i] = 0.f; g_c[i] = 0.f; }
    if (i < GRP*GBLK) g_flags[i] = 0u;
}

// M[g][d] = sum_h Wih[g][h]*embW[h][d], g-pair FMA2, smem layout [h][g]
__global__ void k_fuseM(const float* __restrict__ Wih, const float* __restrict__ embW, int which){
    __shared__ __align__(16) float ws[512*8];
    int tid = threadIdx.x, g0 = blockIdx.x*8;
    for (int i = tid; i < 4096; i += 320)
        ws[(i&511)*8 + (i>>9)] = Wih[(size_t)(g0 + (i>>9))*Hh + (i&511)];
    __syncthreads();
    if (tid < Dd){
        unsigned long long acc2[4] = {0ULL,0ULL,0ULL,0ULL};
        const unsigned long long* wsu = (const unsigned long long*)ws;
        for (int h = 0; h < Hh; h++){
            unsigned long long e2 = pack2(embW[h*Dd + tid]);
            #pragma unroll
            for (int q = 0; q < 4; q++) fma2(acc2[q], wsu[h*4+q], e2);
        }
        float* M = g_MT[which];
        int dd = tid>>1, lo = tid&1;
        #pragma unroll
        for (int q = 0; q < 4; q++){
            float2 f = up2(acc2[q]);
            M[dd*4096 + (g0+q*2)*2 + lo]   = f.x;
            M[dd*4096 + (g0+q*2+1)*2 + lo] = f.y;
        }
    }
}

// xg for 16 rows (same t) per block; writes [t][g][b]
__global__ void k_xg(const int* __restrict__ idxs, int sstride,
                     const float* __restrict__ wv,
                     const float* __restrict__ bih, const float* __restrict__ bhh,
                     int which){
    __shared__ __align__(16) float wvs[16*304];
    __shared__ int sidx[16];
    int tid = threadIdx.x;
    int row16 = blockIdx.x*16, t = row16>>5, b0 = row16&31;
    if (tid < 16) sidx[tid] = idxs[(b0+tid)*sstride + t];
    __syncthreads();
    const float4* wv4 = (const float4*)wv;
    for (int i = tid; i < 1200; i += 256){
        int r = i/75, d4 = i - r*75;
        *(float4*)&wvs[r*304 + d4*4] = wv4[(size_t)sidx[r]*75 + d4];
    }
    __syncthreads();
    const unsigned long long* Mu = (const unsigned long long*)g_MT[which];
    const unsigned long long* wu = (const unsigned long long*)wvs;
    float* xg = which ? g_xgD : g_xgE;
    for (int pass = 0; pass < 4; pass++){
        unsigned long long a0[16], a1[16];
        #pragma unroll
        for (int r = 0; r < 16; r++){ a0[r] = 0ULL; a1[r] = 0ULL; }
        int g = pass*512 + tid;
        for (int dd = 0; dd < 150; dd++){
            unsigned long long m0 = Mu[dd*2048 + g];
            unsigned long long m1 = Mu[dd*2048 + g + 256];
            #pragma unroll
            for (int r = 0; r < 16; r++){
                unsigned long long w2 = wu[r*152 + dd];
                fma2(a0[r], m0, w2);
                fma2(a1[r], m1, w2);
            }
        }
        float bs0 = bih[g] + bhh[g], bs1 = bih[g+256] + bhh[g+256];
        size_t base0 = ((size_t)t*Gg + g)*Bb + b0;
        size_t base1 = ((size_t)t*Gg + g + 256)*Bb + b0;
        #pragma unroll
        for (int r = 0; r < 16; r++){
            float2 f0 = up2(a0[r]), f1 = up2(a1[r]);
            xg[base0 + r] = f0.x + f0.y + bs0;
            xg[base1 + r] = f1.x + f1.y + bs1;
        }
    }
}

// ---------------- persistent LSTM: 4 independent groups of 32 blocks ----------------
// block = (group grp, kgl): owns k in [kgl*16, kgl*16+16) for batches [grp*8, grp*8+8).
// 64 gate-rows x 512 j weights (128KB) in smem; h exchange = 16KB/step within group.
__global__ void __launch_bounds__(256, 1)
k_persist(const float* __restrict__ whh, int which, int nsteps, int p0,
          int use_mask, int store_dech, unsigned bar_base){
    extern __shared__ __align__(16) float dsm[];
    float* ws = dsm;
    float* hs = dsm + HS_OFF2;
    float* sacc = dsm + SACC_OFF2;
    int tid = threadIdx.x, kg = blockIdx.x;
    int grp = kg >> 5, kgl = kg & 31;
    int k0 = kgl*KPB, bg0 = grp*BPG;

    // stage weights once: logical row rr = gate*16+kk -> global row gate*512+k0+kk,
    // stored at psi(rr) = (rr&3)*8 + ((rr>>2)&7) + (rr>>5)*32 so warp row-sets
    // {rw*32 + rgrp*4 + r : rgrp 0..7} are psi-consecutive (single-phase LDS.128).
    const float4* w4 = (const float4*)whh;
    for (int i = tid; i < 8192; i += 256){
        int rr = i>>7, j4 = i&127;
        int gate = rr>>4, kk = rr&15;
        int psi = (rr&3)*8 + ((rr>>2)&7) + (rr>>5)*32;
        *(float4*)&ws[psi*WSTR + j4*4] = w4[(size_t)(gate*Hh + k0 + kk)*128 + j4];
    }

    // persistent cell state: tid<128: cell (kk = tid>>3, bl = tid&7)
    int kk = 0, bl = 0, k = 0, bglob = 0, mylen = 0x7fffffff;
    float c_reg = 0.f, h_own = 0.f;
    if (tid < 128){
        kk = tid>>3; bl = tid&7; k = k0 + kk; bglob = bg0 + bl;
        c_reg = g_c[k*32 + bglob];
        h_own = g_h[p0][bglob*Hh + k];
        if (use_mask) mylen = g_clen[bglob];
    }
    // GEMV mapping: warp = (js 0..3 j-split, rw 0..1 row-half); lane = (rgrp 0..7, bgrp 0..3)
    // thread: 4 rows (rw*32+rgrp*4+r) x 2 batches (bgrp*2, bgrp*2+1) x 128 j
    int wid = tid>>5, lane = tid&31;
    int js = wid & 3, rw = wid >> 2;
    int rgrp = lane >> 2, bgrp = lane & 3;
    int jbase = js*128;
    const float* xg = which ? g_xgD : g_xgE;
    volatile unsigned* flg = (volatile unsigned*)(g_flags + grp*GBLK);
    __syncthreads();

    int p = p0;
    for (int t = 0; t < nsteps; t++){
        // prefetch xg[t] (DRAM) overlapping the wait + stage
        float pv0 = 0.f, pv1 = 0.f, pv2 = 0.f, pv3 = 0.f;
        if (tid < 128){
            size_t xb = ((size_t)t*Gg + k)*Bb + bglob;
            pv0 = __ldg(&xg[xb]);
            pv1 = __ldg(&xg[xb + 512*Bb]);
            pv2 = __ldg(&xg[xb + 1024*Bb]);
            pv3 = __ldg(&xg[xb + 1536*Bb]);
        }

        // wait for all 32 group blocks to have published h(t)
        unsigned tgt = bar_base + (unsigned)t;
        if (tgt){
            if (wid == 0){
                while (!__all_sync(0xffffffffu, ldvol((const unsigned*)&flg[lane]) >= tgt)) {}
                __threadfence();
            }
        }
        __syncthreads();

        // stage h(t): 8 batches x 512 -> hs[bl][WSTR]
        const ulonglong2* hg = (const ulonglong2*)(g_h[p] + (size_t)bg0*Hh);
        #pragma unroll
        for (int q = 0; q < 4; q++){
            int i = tid + q*256;
            int row = i>>7, c4 = i&127;
            *(ulonglong2*)&hs[row*WSTR + c4*4] = ldcg128(&hg[row*128 + c4]);
        }
        __syncthreads();

        // GEMV: 4 rows x 2 batches x 128 j
        unsigned long long acc[4][2];
        #pragma unroll
        for (int r = 0; r < 4; r++){ acc[r][0] = 0ULL; acc[r][1] = 0ULL; }
        int psib = rw*32 + rgrp;   // psi of (rw,rgrp,r) is psib + r*8
        #pragma unroll 2
        for (int it = 0; it < 32; it++){
            int j4 = jbase + it*4;
            ulonglong2 h0 = *(const ulonglong2*)&hs[(bgrp*2)*WSTR + j4];
            ulonglong2 h1 = *(const ulonglong2*)&hs[(bgrp*2+1)*WSTR + j4];
            #pragma unroll
            for (int r = 0; r < 4; r++){
                ulonglong2 wv = *(const ulonglong2*)&ws[(psib + r*8)*WSTR + j4];
                fma2(acc[r][0], wv.x, h0.x); fma2(acc[r][0], wv.y, h0.y);
                fma2(acc[r][1], wv.x, h1.x); fma2(acc[r][1], wv.y, h1.y);
            }
        }
        #pragma unroll
        for (int r = 0; r < 4; r++){
            int row = rw*32 + rgrp*4 + r;
            float2 f0 = up2(acc[r][0]), f1 = up2(acc[r][1]);
            sacc[(js*64 + row)*9 + bgrp*2]     = f0.x + f0.y;
            sacc[(js*64 + row)*9 + bgrp*2 + 1] = f1.x + f1.y;
        }
        __syncthreads();

        if (tid < 128){
            float vi = pv0, vf = pv1, vg = pv2, vo = pv3;
            #pragma unroll
            for (int q = 0; q < 4; q++){
                vi += sacc[(q*64 + 0*16 + kk)*9 + bl];
                vf += sacc[(q*64 + 1*16 + kk)*9 + bl];
                vg += sacc[(q*64 + 2*16 + kk)*9 + bl];
                vo += sacc[(q*64 + 3*16 + kk)*9 + bl];
            }
            float ig = 1.f/(1.f + expf(-vi));
            float fg = 1.f/(1.f + expf(-vf));
            float gg = tanhf(vg);
            float og = 1.f/(1.f + expf(-vo));
            float nc = fg*c_reg + ig*gg;
            float nh = og*tanhf(nc);
            if (t < mylen){ c_reg = nc; h_own = nh; }
            g_h[p^1][bglob*Hh + k] = h_own;
            if (store_dech) g_dech[(size_t)(bglob*LQ1 + t)*Hh + k] = h_own;
        }
        __syncthreads();
        if (tid == 0){
            __threadfence();
            flg[kgl] = bar_base + (unsigned)t + 1u;
        }
        p ^= 1;
    }
    if (tid < 128) g_c[k*32 + bglob] = c_reg;
}

// GEMM: block = 64 rows x 128 v; thread = 8 rows x 4 v (FMA2 over k pairs)
__global__ void __launch_bounds__(256)
k_proj(const float* __restrict__ pW, const float* __restrict__ pb,
       float* __restrict__ out){
    __shared__ __align__(16) float As[64*36];
    __shared__ __align__(16) float Bs[128*36];
    int tid = threadIdx.x;
    int row0 = blockIdx.x*64, v0 = blockIdx.y*128;
    int vg = tid&31, rgrp = tid>>5;
    unsigned long long acc[8][4];
    #pragma unroll
    for (int r = 0; r < 8; r++)
        #pragma unroll
        for (int v = 0; v < 4; v++) acc[r][v] = 0ULL;
    const float4* pW4 = (const float4*)pW;
    for (int kc = 0; kc < Hh; kc += 32){
        __syncthreads();
        for (int i = tid; i < 2048; i += 256)
            As[(i>>5)*36 + (i&31)] = g_dech[(size_t)(row0 + (i>>5))*Hh + kc + (i&31)];
        for (int i = tid; i < 1024; i += 256){
            int vv = i>>3, q = i&7, v = v0 + vv;
            float4 val = (v < Vv) ? pW4[(size_t)v*128 + (kc>>2) + q]
                                  : make_float4(0.f,0.f,0.f,0.f);
            ulonglong2* dst = (ulonglong2*)Bs + (size_t)vv*9 + q;
            *dst = *(const ulonglong2*)&val;
        }
        __syncthreads();
        const ulonglong2* Au = (const ulonglong2*)As;
        const ulonglong2* Bu = (const ulonglong2*)Bs;
        #pragma unroll
        for (int kk2 = 0; kk2 < 8; kk2++){
            ulonglong2 a2[8], b2[4];
            #pragma unroll
            for (int r = 0; r < 8; r++) a2[r] = Au[(rgrp*8 + r)*9 + kk2];
            #pragma unroll
            for (int v = 0; v < 4; v++) b2[v] = Bu[(vg + 32*v)*9 + kk2];
            #pragma unroll
            for (int r = 0; r < 8; r++)
                #pragma unroll
                for (int v = 0; v < 4; v++){
                    fma2(acc[r][v], a2[r].x, b2[v].x);
                    fma2(acc[r][v], a2[r].y, b2[v].y);
                }
        }
    }
    #pragma unroll
    for (int r = 0; r < 8; r++){
        int row = row0 + rgrp*8 + r;
        if (row < NR){
            #pragma unroll
            for (int v = 0; v < 4; v++){
                int vc = v0 + vg + 32*v;
                if (vc < Vv){
                    float2 f = up2(acc[r][v]);
                    out[(size_t)row*Vv + vc] = f.x + f.y + pb[vc];
                }
            }
        }
    }
}

__global__ void k_softmax(const int* __restrict__ qw, float* __restrict__ out){
    int row = blockIdx.x, tid = threadIdx.x;
    int b = row/LQ1, t = row - b*LQ1;
    float* p = out + (size_t)row*Vv;
    float4* p4 = (float4*)p;
    if (qw[b*30 + t] == 0){
        float4 fill = make_float4(NEGLOGV, NEGLOGV, NEGLOGV, NEGLOGV);
        for (int i = tid; i < 12500; i += 256) p4[i] = fill;
        return;
    }
    __shared__ float red[256];
    float m = -1e30f;
    for (int i = tid; i < 12500; i += 256){
        float4 x = p4[i];
        m = fmaxf(m, fmaxf(fmaxf(x.x, x.y), fmaxf(x.z, x.w)));
    }
    red[tid] = m; __syncthreads();
    for (int s = 128; s > 0; s >>= 1){
        if (tid < s) red[tid] = fmaxf(red[tid], red[tid+s]);
        __syncthreads();
    }
    m = red[0]; __syncthreads();
    float sum = 0.f;
    for (int i = tid; i < 12500; i += 256){
        float4 x = p4[i];
        sum += __expf(x.x - m) + __expf(x.y - m) + __expf(x.z - m) + __expf(x.w - m);
    }
    red[tid] = sum; __syncthreads();
    for (int s = 128; s > 0; s >>= 1){
        if (tid < s) red[tid] += red[tid+s];
        __syncthreads();
    }
    float lse = m + logf(red[0]);
    __syncthreads();
    for (int i = tid; i < 12500; i += 256){
        float4 x = p4[i];
        x.x -= lse; x.y -= lse; x.z -= lse; x.w -= lse;
        p4[i] = x;
    }
}

extern "C" void kernel_launch(void* const* d_in, const int* in_sizes, int n_in,
                              void* d_out, int out_size){
    const int*   cw   = (const int*)d_in[0];
    const int*   qw   = (const int*)d_in[1];
    const float* wv   = (const float*)d_in[2];
    const float* embW = (const float*)d_in[3];
    const float* eWih = (const float*)d_in[4];
    const float* eWhh = (const float*)d_in[5];
    const float* ebih = (const float*)d_in[6];
    const float* ebhh = (const float*)d_in[7];
    const float* dWih = (const float*)d_in[8];
    const float* dWhh = (const float*)d_in[9];
    const float* dbih = (const float*)d_in[10];
    const float* dbhh = (const float*)d_in[11];
    const float* pW   = (const float*)d_in[12];
    const float* pb   = (const float*)d_in[13];
    float* out = (float*)d_out;

    static int smem_set = 0;
    if (!smem_set){
        cudaFuncSetAttribute(k_persist, cudaFuncAttributeMaxDynamicSharedMemorySize, SMEM_P2);
        smem_set = 1;
    }

    k_clen<<<1, 256>>>(cw);
    k_zero<<<64, 256>>>();
    k_fuseM<<<256, 320>>>(eWih, embW, 0);
    k_fuseM<<<256, 320>>>(dWih, embW, 1);
    k_xg<<<800, 256>>>(cw, LCc, wv, ebih, ebhh, 0);
    k_xg<<<58, 256>>>(qw, 30, wv, dbih, dbhh, 1);
    k_persist<<<128, 256, SMEM_P2>>>(eWhh, 0, LCc, 0, 1, 0, 0u);
    k_persist<<<128, 256, SMEM_P2>>>(dWhh, 1, LQ1, LCc & 1, 0, 1, (unsigned)LCc);
    k_proj<<<dim3(15, 391), 256>>>(pW, pb, out);
    k_softmax<<<NR, 256>>>(qw, out);
}